// round 15
// baseline (speedup 1.0000x reference)
#include <cuda_runtime.h>
#include <math.h>

#define BSZ   32768
#define HDIM  256
#define INF_STEPS 10

// ---------------------------------------------------------------------------
// Device scratch
// ---------------------------------------------------------------------------
__device__ __align__(16) float g_cond1[BSZ * HDIM];
__device__ __align__(16) float g_cskip[BSZ * HDIM];
__device__ __align__(16) float g_h    [BSZ * HDIM];
__device__ __align__(16) float g_t    [BSZ * HDIM];
__device__ __align__(16) float g_skip [BSZ * HDIM];
__device__ __align__(16) float g_x    [BSZ * 4];
__device__ __align__(16) float g_noise[INF_STEPS * BSZ * 4];
__device__ __align__(16) float g_v1   [INF_STEPS * HDIM];
__device__ __align__(16) float g_vsk  [INF_STEPS * HDIM];

// ---------------------------------------------------------------------------
// threefry2x32 (exact JAX 20-round block) + partitionable normal
// ---------------------------------------------------------------------------
__host__ __device__ __forceinline__
void threefry2x32(unsigned k0, unsigned k1, unsigned c0, unsigned c1,
                  unsigned& o0, unsigned& o1)
{
    unsigned ks0 = k0, ks1 = k1, ks2 = k0 ^ k1 ^ 0x1BD11BDAu;
    unsigned x0 = c0 + ks0, x1 = c1 + ks1;
#define TFR(r) { x0 += x1; x1 = (x1 << (r)) | (x1 >> (32 - (r))); x1 ^= x0; }
    TFR(13) TFR(15) TFR(26) TFR(6)   x0 += ks1; x1 += ks2 + 1u;
    TFR(17) TFR(29) TFR(16) TFR(24)  x0 += ks2; x1 += ks0 + 2u;
    TFR(13) TFR(15) TFR(26) TFR(6)   x0 += ks0; x1 += ks1 + 3u;
    TFR(17) TFR(29) TFR(16) TFR(24)  x0 += ks1; x1 += ks2 + 4u;
    TFR(13) TFR(15) TFR(26) TFR(6)   x0 += ks2; x1 += ks0 + 5u;
#undef TFR
    o0 = x0; o1 = x1;
}
__device__ __forceinline__ float erfinv_xla(float x)
{
    float w = -log1pf(-x * x), p;
    if (w < 5.0f) {
        w -= 2.5f;
        p = 2.81022636e-08f;
        p = fmaf(p, w, 3.43273939e-07f);  p = fmaf(p, w, -3.5233877e-06f);
        p = fmaf(p, w, -4.39150654e-06f); p = fmaf(p, w, 0.00021858087f);
        p = fmaf(p, w, -0.00125372503f);  p = fmaf(p, w, -0.00417768164f);
        p = fmaf(p, w, 0.246640727f);     p = fmaf(p, w, 1.50140941f);
    } else {
        w = sqrtf(w) - 3.0f;
        p = -0.000200214257f;
        p = fmaf(p, w, 0.000100950558f);  p = fmaf(p, w, 0.00134934322f);
        p = fmaf(p, w, -0.00367342844f);  p = fmaf(p, w, 0.00573950773f);
        p = fmaf(p, w, -0.0076224613f);   p = fmaf(p, w, 0.00943887047f);
        p = fmaf(p, w, 1.00167406f);      p = fmaf(p, w, 2.83297682f);
    }
    return p * x;
}
__global__ void rng_normal_kernel(float* out, int n, unsigned k0, unsigned k1)
{
    int i = blockIdx.x * blockDim.x + threadIdx.x;
    if (i >= n) return;
    unsigned o0, o1;
    threefry2x32(k0, k1, 0u, (unsigned)i, o0, o1);
    unsigned bits = o0 ^ o1;
    float f = __uint_as_float((bits >> 9) | 0x3f800000u) - 1.0f;
    const float lo = -0.99999994f;
    float u = fmaxf(lo, f * 2.0f + lo);
    out[i] = 1.41421356237f * erfinv_xla(u);
}
__device__ __forceinline__ float gelu_f(float x)
{
    return 0.5f * x * (1.0f + erff(x * 0.70710678118654752f));
}

// ---------------------------------------------------------------------------
// Timestep embedding projections (tiny)
// ---------------------------------------------------------------------------
__global__ void temb_kernel(const float* __restrict__ time_w, const float* __restrict__ time_b,
                            const float* __restrict__ blk0_w1, const float* __restrict__ blk0_skip_w)
{
    __shared__ float se[HDIM], temb[HDIM];
    int s = blockIdx.x, j = threadIdx.x;
    double t = (double)(90 - 10 * s);
    const double cfreq = -9.210340371976184 / 127.0;
    if (j < 128) se[j] = (float)sin(t * exp((double)j * cfreq));
    else         se[j] = (float)cos(t * exp((double)(j - 128) * cfreq));
    __syncthreads();
    float acc = time_b[j];
    for (int k = 0; k < HDIM; k++) acc = fmaf(se[k], time_w[k * HDIM + j], acc);
    temb[j] = gelu_f(acc);
    __syncthreads();
    float a1 = 0.0f, as = 0.0f;
    for (int k = 0; k < HDIM; k++) {
        float tv = temb[k];
        a1 = fmaf(tv, blk0_w1    [(256 + k) * HDIM + j], a1);
        as = fmaf(tv, blk0_skip_w[(256 + k) * HDIM + j], as);
    }
    g_v1 [s * HDIM + j] = a1;
    g_vsk[s * HDIM + j] = as;
}

// ---------------------------------------------------------------------------
// Build h1/skip
// ---------------------------------------------------------------------------
__global__ void build_kernel(const float* __restrict__ w1, const float* __restrict__ ws, int step)
{
    int idx = blockIdx.x * 256 + threadIdx.x;
    int n = idx & 255, m = idx >> 8;
    float x0 = g_x[m*4+0], x1 = g_x[m*4+1], x2 = g_x[m*4+2], x3 = g_x[m*4+3];
    float h1 = g_cond1[idx] + g_v1[step * HDIM + n];
    h1 = fmaf(x0, w1[512*HDIM+n], h1); h1 = fmaf(x1, w1[513*HDIM+n], h1);
    h1 = fmaf(x2, w1[514*HDIM+n], h1); h1 = fmaf(x3, w1[515*HDIM+n], h1);
    g_t[idx] = gelu_f(h1);
    float sk = g_cskip[idx] + g_vsk[step * HDIM + n];
    sk = fmaf(x0, ws[512*HDIM+n], sk); sk = fmaf(x1, ws[513*HDIM+n], sk);
    sk = fmaf(x2, ws[514*HDIM+n], sk); sk = fmaf(x3, ws[515*HDIM+n], sk);
    g_skip[idx] = sk;
}

// ---------------------------------------------------------------------------
// FFMA2 SGEMM v3: 8(M)x8(N) microtiles, M-packed accumulators.
// CTA 128x128, 256 threads, 2 CTAs/SM (16 warps/SM), double-buffered smem.
// A operands load pre-packed (ulonglong2 from [k][m] tile) -> no pack movs.
// EPI: 1=bias, 2=gelu, 4=residual
// ---------------------------------------------------------------------------
__device__ __forceinline__ unsigned long long pack2(float lo, float hi)
{
    unsigned long long r;
    asm("mov.b64 %0, {%1, %2};" : "=l"(r) : "f"(lo), "f"(hi));
    return r;
}
__device__ __forceinline__ void unpack2(unsigned long long v, float& lo, float& hi)
{
    asm("mov.b64 {%0, %1}, %2;" : "=f"(lo), "=f"(hi) : "l"(v));
}
__device__ __forceinline__ unsigned long long ffma2(unsigned long long a,
                                                    unsigned long long b,
                                                    unsigned long long c)
{
    unsigned long long d;
    asm("fma.rn.f32x2 %0, %1, %2, %3;" : "=l"(d) : "l"(a), "l"(b), "l"(c));
    return d;
}

#define GBM 128
#define GBN 128
#define GBK 16
#define KTILES 16

template <int EPI>
__global__ __launch_bounds__(256, 2)
void sgemm_kernel(const float* __restrict__ A, const float* __restrict__ W,
                  const float* __restrict__ bias, const float* R, float* C)
{
    __shared__ float As[2][GBK][GBM + 4];   // [buf][k][m], row stride 528B
    __shared__ float Bs[2][GBK][GBN];

    const int K = 256, N = 256;
    int tid = threadIdx.x;              // 0..255
    int tx = tid & 15, ty = tid >> 4;   // tx: n-group (8 cols), ty: m-group (8 rows)
    int m0 = blockIdx.y * GBM;
    int n0 = blockIdx.x * GBN;

    // Per-thread load coords: 2 float4 chunks each for A and B
    int am[2], akq[2], bkr[2], bnq[2];
    #pragma unroll
    for (int l = 0; l < 2; l++) {
        int lin = tid + l * 256;        // 0..511
        am[l]  = lin >> 2;  akq[l] = lin & 3;
        bkr[l] = lin >> 5;  bnq[l] = lin & 31;
    }
    const float* Ap[2];
    const float* Bp[2];
    #pragma unroll
    for (int l = 0; l < 2; l++) {
        Ap[l] = A + (size_t)(m0 + am[l]) * K + akq[l] * 4;
        Bp[l] = W + (size_t)bkr[l] * N + n0 + bnq[l] * 4;
    }

    // Prologue: tile 0 -> buffer 0
    #pragma unroll
    for (int l = 0; l < 2; l++) {
        float4 a = *(const float4*)Ap[l];
        As[0][akq[l]*4 + 0][am[l]] = a.x;
        As[0][akq[l]*4 + 1][am[l]] = a.y;
        As[0][akq[l]*4 + 2][am[l]] = a.z;
        As[0][akq[l]*4 + 3][am[l]] = a.w;
        *(float4*)&Bs[0][bkr[l]][bnq[l]*4] = *(const float4*)Bp[l];
    }
    __syncthreads();

    unsigned long long acc[4][8];       // [m-pair][n], 64 regs
    #pragma unroll
    for (int p = 0; p < 4; p++)
        #pragma unroll
        for (int j = 0; j < 8; j++) acc[p][j] = 0ull;

    for (int kt = 0; kt < KTILES; kt++) {
        int cur = kt & 1;
        float4 pa[2], pb[2];
        if (kt < KTILES - 1) {
            int k0 = (kt + 1) * GBK;
            #pragma unroll
            for (int l = 0; l < 2; l++) {
                pa[l] = *(const float4*)(Ap[l] + k0);
                pb[l] = *(const float4*)(Bp[l] + (size_t)k0 * N);
            }
        }

        #pragma unroll
        for (int k = 0; k < GBK; k++) {
            // A: 8 rows as 4 pre-packed f32x2 pairs
            const ulonglong2* apq = (const ulonglong2*)&As[cur][k][ty * 8];
            ulonglong2 q0 = apq[0], q1 = apq[1];
            unsigned long long a[4] = { q0.x, q0.y, q1.x, q1.y };
            float4 b0 = *(const float4*)&Bs[cur][k][tx * 8];
            float4 b1 = *(const float4*)&Bs[cur][k][tx * 8 + 4];
            unsigned long long bb[8] = {
                pack2(b0.x, b0.x), pack2(b0.y, b0.y),
                pack2(b0.z, b0.z), pack2(b0.w, b0.w),
                pack2(b1.x, b1.x), pack2(b1.y, b1.y),
                pack2(b1.z, b1.z), pack2(b1.w, b1.w) };
            #pragma unroll
            for (int p = 0; p < 4; p++)
                #pragma unroll
                for (int j = 0; j < 8; j++)
                    acc[p][j] = ffma2(a[p], bb[j], acc[p][j]);
        }

        if (kt < KTILES - 1) {
            int nxt = cur ^ 1;
            #pragma unroll
            for (int l = 0; l < 2; l++) {
                As[nxt][akq[l]*4 + 0][am[l]] = pa[l].x;
                As[nxt][akq[l]*4 + 1][am[l]] = pa[l].y;
                As[nxt][akq[l]*4 + 2][am[l]] = pa[l].z;
                As[nxt][akq[l]*4 + 3][am[l]] = pa[l].w;
                *(float4*)&Bs[nxt][bkr[l]][bnq[l]*4] = pb[l];
            }
            __syncthreads();
        }
    }

    // Epilogue: thread owns rows m0+ty*8..+7 (4 pairs), cols n0+tx*8..+7
    float bv[8];
    #pragma unroll
    for (int j = 0; j < 8; j++)
        bv[j] = (EPI & 1) ? bias[n0 + tx * 8 + j] : 0.0f;

    #pragma unroll
    for (int p = 0; p < 4; p++) {
        float r0[8], r1[8];
        #pragma unroll
        for (int j = 0; j < 8; j++) unpack2(acc[p][j], r0[j], r1[j]);
        int mA = m0 + ty * 8 + 2 * p;
        #pragma unroll
        for (int h = 0; h < 2; h++) {
            float* rv = h ? r1 : r0;
            int m = mA + h;
            #pragma unroll
            for (int j = 0; j < 8; j++) {
                float c = rv[j] + bv[j];
                if (EPI & 2) c = gelu_f(c);
                rv[j] = c;
            }
            if (EPI & 4) {
                float4 x0 = *(const float4*)&R[(size_t)m * N + n0 + tx * 8];
                float4 x1 = *(const float4*)&R[(size_t)m * N + n0 + tx * 8 + 4];
                rv[0] += x0.x; rv[1] += x0.y; rv[2] += x0.z; rv[3] += x0.w;
                rv[4] += x1.x; rv[5] += x1.y; rv[6] += x1.z; rv[7] += x1.w;
            }
            *(float4*)&C[(size_t)m * N + n0 + tx * 8] =
                make_float4(rv[0], rv[1], rv[2], rv[3]);
            *(float4*)&C[(size_t)m * N + n0 + tx * 8 + 4] =
                make_float4(rv[4], rv[5], rv[6], rv[7]);
        }
    }
}

// ---------------------------------------------------------------------------
// pred = h @ final_w + final_b ; diffusion x-update
// ---------------------------------------------------------------------------
__global__ void final_update_kernel(const float* __restrict__ fw, const float* __restrict__ fb,
                                    int step, float c1, float sqrt_a, float sqrt_b,
                                    int add_noise, float* out)
{
    __shared__ float sfw[HDIM * 4];
    int tid = threadIdx.x;
    #pragma unroll
    for (int l = 0; l < 4; l++) sfw[tid + l * 256] = fw[tid + l * 256];
    __syncthreads();
    int m = blockIdx.x * 64 + (tid >> 2), a = tid & 3;
    const float4* h4 = (const float4*)&g_h[(size_t)m * HDIM];
    float acc = 0.0f;
    #pragma unroll 8
    for (int k4 = 0; k4 < HDIM / 4; k4++) {
        float4 hv = h4[k4];
        acc = fmaf(hv.x, sfw[(k4*4+0)*4+a], acc);
        acc = fmaf(hv.y, sfw[(k4*4+1)*4+a], acc);
        acc = fmaf(hv.z, sfw[(k4*4+2)*4+a], acc);
        acc = fmaf(hv.w, sfw[(k4*4+3)*4+a], acc);
    }
    float pred = acc + fb[a];
    float x = g_x[m*4+a];
    x = (x - c1 * pred) / sqrt_a;
    if (add_noise) x += sqrt_b * g_noise[((size_t)step * BSZ + m) * 4 + a];
    g_x[m*4+a] = x;
    if (out) out[m*4+a] = fminf(1.0f, fmaxf(-1.0f, x));
}

// ---------------------------------------------------------------------------
// Launch
// ---------------------------------------------------------------------------
extern "C" void kernel_launch(void* const* d_in, const int* in_sizes, int n_in,
                              void* d_out, int out_size)
{
    (void)n_in; (void)out_size;
    const float *features, *cond_w, *cond_b, *time_w, *time_b;
    const float *blk0_w1, *blk0_b1, *blk0_w2, *blk0_b2, *blk0_skip_w, *blk0_skip_b;
    const float *blks_w1, *blks_b1, *blks_w2, *blks_b2, *final_w, *final_b;

    if (in_sizes[0] == BSZ * HDIM) {
        features    = (const float*)d_in[0];  cond_w      = (const float*)d_in[1];
        cond_b      = (const float*)d_in[2];  time_w      = (const float*)d_in[3];
        time_b      = (const float*)d_in[4];  blk0_w1     = (const float*)d_in[5];
        blk0_b1     = (const float*)d_in[6];  blk0_w2     = (const float*)d_in[7];
        blk0_b2     = (const float*)d_in[8];  blk0_skip_w = (const float*)d_in[9];
        blk0_skip_b = (const float*)d_in[10]; blks_w1     = (const float*)d_in[11];
        blks_b1     = (const float*)d_in[12]; blks_w2     = (const float*)d_in[13];
        blks_b2     = (const float*)d_in[14]; final_w     = (const float*)d_in[15];
        final_b     = (const float*)d_in[16];
    } else {
        blk0_b1     = (const float*)d_in[0];  blk0_b2     = (const float*)d_in[1];
        blk0_skip_b = (const float*)d_in[2];  blk0_skip_w = (const float*)d_in[3];
        blk0_w1     = (const float*)d_in[4];  blk0_w2     = (const float*)d_in[5];
        blks_b1     = (const float*)d_in[6];  blks_b2     = (const float*)d_in[7];
        blks_w1     = (const float*)d_in[8];  blks_w2     = (const float*)d_in[9];
        cond_b      = (const float*)d_in[10]; cond_w      = (const float*)d_in[11];
        features    = (const float*)d_in[12]; final_b     = (const float*)d_in[13];
        final_w     = (const float*)d_in[14]; time_b      = (const float*)d_in[15];
        time_w      = (const float*)d_in[16];
    }

    float *p_cond1, *p_cskip, *p_h, *p_t, *p_skip, *p_x, *p_noise;
    cudaGetSymbolAddress((void**)&p_cond1, g_cond1);
    cudaGetSymbolAddress((void**)&p_cskip, g_cskip);
    cudaGetSymbolAddress((void**)&p_h,     g_h);
    cudaGetSymbolAddress((void**)&p_t,     g_t);
    cudaGetSymbolAddress((void**)&p_skip,  g_skip);
    cudaGetSymbolAddress((void**)&p_x,     g_x);
    cudaGetSymbolAddress((void**)&p_noise, g_noise);

    float betas[100], acps[100], cp = 1.0f;
    for (int i = 0; i < 100; i++) {
        betas[i] = (float)(1e-4 + (0.02 - 1e-4) * ((double)i / 99.0));
        cp *= (1.0f - betas[i]);
        acps[i] = cp;
    }
    unsigned kx0, kx1, kn0, kn1;
    threefry2x32(0u, 42u, 0u, 999u, kx0, kx1);
    threefry2x32(0u, 42u, 0u, 7u,   kn0, kn1);

    rng_normal_kernel<<<512, 256>>>(p_x, BSZ * 4, kx0, kx1);
    rng_normal_kernel<<<5120, 256>>>(p_noise, INF_STEPS * BSZ * 4, kn0, kn1);
    temb_kernel<<<INF_STEPS, 256>>>(time_w, time_b, blk0_w1, blk0_skip_w);

    dim3 gg(2, BSZ / GBM);

    sgemm_kernel<1><<<gg, 256>>>(features, cond_w, cond_b, nullptr, p_h);
    sgemm_kernel<1><<<gg, 256>>>(p_h, blk0_w1, blk0_b1, nullptr, p_cond1);
    sgemm_kernel<1><<<gg, 256>>>(p_h, blk0_skip_w, blk0_skip_b, nullptr, p_cskip);

    for (int s = 0; s < INF_STEPS; s++) {
        int t = 90 - 10 * s;
        float b = betas[t], a = 1.0f - b, acp = acps[t];
        float c1 = b / sqrtf(1.0f - acp), sa = sqrtf(a), sb = sqrtf(b);

        build_kernel<<<BSZ, 256>>>(blk0_w1, blk0_skip_w, s);
        sgemm_kernel<7><<<gg, 256>>>(p_t, blk0_w2, blk0_b2, p_skip, p_h);
        for (int i = 0; i < 3; i++) {
            sgemm_kernel<3><<<gg, 256>>>(p_h, blks_w1 + i * 65536,
                                         blks_b1 + i * 256, nullptr, p_t);
            sgemm_kernel<7><<<gg, 256>>>(p_t, blks_w2 + i * 65536,
                                         blks_b2 + i * 256, p_h, p_h);
        }
        final_update_kernel<<<BSZ / 64, 256>>>(final_w, final_b, s, c1, sa, sb,
                                               (t > 0) ? 1 : 0,
                                               (s == INF_STEPS - 1) ? (float*)d_out : nullptr);
    }
}

// round 16
// speedup vs baseline: 1.0954x; 1.0954x over previous
#include <cuda_runtime.h>
#include <math.h>
#include <stdint.h>

#define BSZ   32768
#define HDIM  256
#define INF_STEPS 10

// ---------------------------------------------------------------------------
// Device scratch
// ---------------------------------------------------------------------------
__device__ __align__(16) float g_cond1[BSZ * HDIM];
__device__ __align__(16) float g_cskip[BSZ * HDIM];
__device__ __align__(16) float g_h    [BSZ * HDIM];
__device__ __align__(16) float g_t    [BSZ * HDIM];
__device__ __align__(16) float g_skip [BSZ * HDIM];
__device__ __align__(16) float g_x    [BSZ * 4];
__device__ __align__(16) float g_noise[INF_STEPS * BSZ * 4];
__device__ __align__(16) float g_v1   [INF_STEPS * HDIM];
__device__ __align__(16) float g_vsk  [INF_STEPS * HDIM];
// Fragment-major tf32 weight planes: [matrix][nblock 0..31][ks 0..31][lane][2]
__device__ __align__(16) float g_wfh  [10 * 65536];
__device__ __align__(16) float g_wfl  [10 * 65536];

// ---- tf32 / mma helpers (validated in R11) ----
__device__ __forceinline__ uint32_t tf32_bits(float a) {
    uint32_t u; asm("cvt.rna.tf32.f32 %0, %1;" : "=r"(u) : "f"(a));
    return u;
}
__device__ __forceinline__ void mma8(float* d, const uint32_t* a, uint32_t b0, uint32_t b1) {
    asm volatile(
        "mma.sync.aligned.m16n8k8.row.col.f32.tf32.tf32.f32 "
        "{%0,%1,%2,%3}, {%4,%5,%6,%7}, {%8,%9}, {%0,%1,%2,%3};"
        : "+f"(d[0]), "+f"(d[1]), "+f"(d[2]), "+f"(d[3])
        : "r"(a[0]), "r"(a[1]), "r"(a[2]), "r"(a[3]), "r"(b0), "r"(b1));
}

// ---- threefry / RNG (exact JAX partitionable path) ----
__host__ __device__ __forceinline__
void threefry2x32(unsigned k0, unsigned k1, unsigned c0, unsigned c1,
                  unsigned& o0, unsigned& o1)
{
    unsigned ks0 = k0, ks1 = k1, ks2 = k0 ^ k1 ^ 0x1BD11BDAu;
    unsigned x0 = c0 + ks0, x1 = c1 + ks1;
#define TFR(r) { x0 += x1; x1 = (x1 << (r)) | (x1 >> (32 - (r))); x1 ^= x0; }
    TFR(13) TFR(15) TFR(26) TFR(6)   x0 += ks1; x1 += ks2 + 1u;
    TFR(17) TFR(29) TFR(16) TFR(24)  x0 += ks2; x1 += ks0 + 2u;
    TFR(13) TFR(15) TFR(26) TFR(6)   x0 += ks0; x1 += ks1 + 3u;
    TFR(17) TFR(29) TFR(16) TFR(24)  x0 += ks1; x1 += ks2 + 4u;
    TFR(13) TFR(15) TFR(26) TFR(6)   x0 += ks2; x1 += ks0 + 5u;
#undef TFR
    o0 = x0; o1 = x1;
}
__device__ __forceinline__ float erfinv_xla(float x)
{
    float w = -log1pf(-x * x), p;
    if (w < 5.0f) {
        w -= 2.5f;
        p = 2.81022636e-08f;
        p = fmaf(p, w, 3.43273939e-07f);  p = fmaf(p, w, -3.5233877e-06f);
        p = fmaf(p, w, -4.39150654e-06f); p = fmaf(p, w, 0.00021858087f);
        p = fmaf(p, w, -0.00125372503f);  p = fmaf(p, w, -0.00417768164f);
        p = fmaf(p, w, 0.246640727f);     p = fmaf(p, w, 1.50140941f);
    } else {
        w = sqrtf(w) - 3.0f;
        p = -0.000200214257f;
        p = fmaf(p, w, 0.000100950558f);  p = fmaf(p, w, 0.00134934322f);
        p = fmaf(p, w, -0.00367342844f);  p = fmaf(p, w, 0.00573950773f);
        p = fmaf(p, w, -0.0076224613f);   p = fmaf(p, w, 0.00943887047f);
        p = fmaf(p, w, 1.00167406f);      p = fmaf(p, w, 2.83297682f);
    }
    return p * x;
}
__global__ void rng_normal_kernel(float* out, int n, unsigned k0, unsigned k1)
{
    int i = blockIdx.x * blockDim.x + threadIdx.x;
    if (i >= n) return;
    unsigned o0, o1;
    threefry2x32(k0, k1, 0u, (unsigned)i, o0, o1);
    unsigned bits = o0 ^ o1;
    float f = __uint_as_float((bits >> 9) | 0x3f800000u) - 1.0f;
    const float lo = -0.99999994f;
    float u = fmaxf(lo, f * 2.0f + lo);
    out[i] = 1.41421356237f * erfinv_xla(u);
}
__device__ __forceinline__ float gelu_f(float x)
{
    return 0.5f * x * (1.0f + erff(x * 0.70710678118654752f));
}

// ---- weight transform (R11-validated): w[k*256+n] -> fragment-major hi/lo ----
// float index i: reg=i&1, lane=(i>>1)&31, ks=(i>>6)&31, nb=i>>11
// n = nb*8 + (lane>>2), k = ks*8 + (lane&3) + reg*4
__global__ void split_w_kernel(const float* __restrict__ w, float* oh, float* ol)
{
    int i = blockIdx.x * 256 + threadIdx.x;
    int reg = i & 1, lane = (i >> 1) & 31, ks = (i >> 6) & 31, nb = i >> 11;
    int n = nb * 8 + (lane >> 2);
    int k = ks * 8 + (lane & 3) + reg * 4;
    float v = w[k * 256 + n];
    float h = __uint_as_float(tf32_bits(v));
    oh[i] = h;
    ol[i] = __uint_as_float(tf32_bits(v - h));
}

// ---- timestep embedding projections ----
__global__ void temb_kernel(const float* __restrict__ time_w, const float* __restrict__ time_b,
                            const float* __restrict__ blk0_w1, const float* __restrict__ blk0_skip_w)
{
    __shared__ float se[HDIM], temb[HDIM];
    int s = blockIdx.x, j = threadIdx.x;
    double t = (double)(90 - 10 * s);
    const double cfreq = -9.210340371976184 / 127.0;
    if (j < 128) se[j] = (float)sin(t * exp((double)j * cfreq));
    else         se[j] = (float)cos(t * exp((double)(j - 128) * cfreq));
    __syncthreads();
    float acc = time_b[j];
    for (int k = 0; k < HDIM; k++) acc = fmaf(se[k], time_w[k * HDIM + j], acc);
    temb[j] = gelu_f(acc);
    __syncthreads();
    float a1 = 0.0f, as = 0.0f;
    for (int k = 0; k < HDIM; k++) {
        float tv = temb[k];
        a1 = fmaf(tv, blk0_w1    [(256 + k) * HDIM + j], a1);
        as = fmaf(tv, blk0_skip_w[(256 + k) * HDIM + j], as);
    }
    g_v1 [s * HDIM + j] = a1;
    g_vsk[s * HDIM + j] = as;
}

// ---- build h1/skip ----
__global__ void build_kernel(const float* __restrict__ w1, const float* __restrict__ ws, int step)
{
    int idx = blockIdx.x * 256 + threadIdx.x;
    int n = idx & 255, m = idx >> 8;
    float x0 = g_x[m*4+0], x1 = g_x[m*4+1], x2 = g_x[m*4+2], x3 = g_x[m*4+3];
    float h1 = g_cond1[idx] + g_v1[step * HDIM + n];
    h1 = fmaf(x0, w1[512*HDIM+n], h1); h1 = fmaf(x1, w1[513*HDIM+n], h1);
    h1 = fmaf(x2, w1[514*HDIM+n], h1); h1 = fmaf(x3, w1[515*HDIM+n], h1);
    g_t[idx] = gelu_f(h1);
    float sk = g_cskip[idx] + g_vsk[step * HDIM + n];
    sk = fmaf(x0, ws[512*HDIM+n], sk); sk = fmaf(x1, ws[513*HDIM+n], sk);
    sk = fmaf(x2, ws[514*HDIM+n], sk); sk = fmaf(x3, ws[515*HDIM+n], sk);
    g_skip[idx] = sk;
}

// ---------------------------------------------------------------------------
// Tensor-core 3xTF32 GEMM with smem staging.
// CTA 128x128, 256 thr = 8 warps (2M x 4N), warp tile 64x32 (mb4 x nb4).
// K staged in chunks of 16 (two k8 steps per stage).
//   A smem: [m][stride 20] raw fp32, split to tf32 hi/lo in regs at use.
//   B smem: fragment-major hi/lo copied from pre-transformed global planes.
// EPI: 1=bias, 2=gelu, 4=residual
// ---------------------------------------------------------------------------
#define ASTR 20

template <int EPI>
__global__ __launch_bounds__(256, 2)
void tgemm_kernel(const float* __restrict__ A,
                  const float* __restrict__ Wfh, const float* __restrict__ Wfl,
                  const float* __restrict__ bias, const float* __restrict__ R,
                  float* __restrict__ C)
{
    __shared__ float  sA [128 * ASTR];          // 10240 B
    __shared__ float2 sBh[2][16][32];           // 8192 B
    __shared__ float2 sBl[2][16][32];           // 8192 B

    int tid  = threadIdx.x;
    int lane = tid & 31, wid = tid >> 5;
    int g = lane >> 2, t = lane & 3;
    int m0 = blockIdx.y * 128;
    int n0 = blockIdx.x * 128;
    int mwarp = (wid & 1) * 64;
    int nwq   = (wid >> 1) * 4;                 // warp's first nb (of CTA's 16)
    int nbg0  = (n0 >> 3);                      // CTA's first global nblock

    // Loader coords
    int la_m = tid >> 1, la_q = (tid & 1) * 2;  // A: 2 float4 per row (k 0-7 / 8-15)
    // B: lin -> (plane handled separately), i = lin>>8, nb = (lin>>4)&15, j = lin&15

    float acc[4][4][4];
    #pragma unroll
    for (int a = 0; a < 4; a++)
        #pragma unroll
        for (int b = 0; b < 4; b++)
            #pragma unroll
            for (int c = 0; c < 4; c++) acc[a][b][c] = 0.0f;

    for (int kt = 0; kt < 16; kt++) {           // 16 stages of k16
        // ---- fill stage ----
        {
            // A: 128 rows x 16 k
            #pragma unroll
            for (int l = 0; l < 2; l++) {
                int q = la_q + l;               // float4 index 0..3 -> k = q*4
                float4 v = *(const float4*)&A[(size_t)(m0 + la_m) * 256 + kt * 16 + q * 4];
                float* d = &sA[la_m * ASTR + q * 4];
                d[0] = v.x; d[1] = v.y; d[2] = v.z; d[3] = v.w;
            }
            // B: both planes, 2 ks8 x 16 nb x 32 lanes (float2)
            #pragma unroll
            for (int l = 0; l < 2; l++) {
                int lin = tid + l * 256;        // 0..511 -> float4 units
                int i  = lin >> 8;
                int nb = (lin >> 4) & 15;
                int j  = lin & 15;
                size_t gi = (size_t)(nbg0 + nb) * 512 + (size_t)(kt * 2 + i) * 16 + j;
                *((float4*)&sBh[i][nb][2 * j]) = ((const float4*)Wfh)[gi];
                *((float4*)&sBl[i][nb][2 * j]) = ((const float4*)Wfl)[gi];
            }
        }
        __syncthreads();

        // ---- compute: two k8 steps ----
        #pragma unroll
        for (int i = 0; i < 2; i++) {
            // Hoist B fragments for this warp's 4 nb
            uint32_t bh[4][2], bl[4][2];
            #pragma unroll
            for (int nb = 0; nb < 4; nb++) {
                float2 h2 = sBh[i][nwq + nb][lane];
                float2 l2 = sBl[i][nwq + nb][lane];
                bh[nb][0] = __float_as_uint(h2.x); bh[nb][1] = __float_as_uint(h2.y);
                bl[nb][0] = __float_as_uint(l2.x); bl[nb][1] = __float_as_uint(l2.y);
            }
            #pragma unroll
            for (int mb = 0; mb < 4; mb++) {
                int mrow = mwarp + mb * 16 + g;
                float r0 = sA[mrow * ASTR + i * 8 + t];
                float r1 = sA[(mrow + 8) * ASTR + i * 8 + t];
                float r2 = sA[mrow * ASTR + i * 8 + t + 4];
                float r3 = sA[(mrow + 8) * ASTR + i * 8 + t + 4];
                uint32_t ah[4], al[4];
                ah[0] = tf32_bits(r0); al[0] = tf32_bits(r0 - __uint_as_float(ah[0]));
                ah[1] = tf32_bits(r1); al[1] = tf32_bits(r1 - __uint_as_float(ah[1]));
                ah[2] = tf32_bits(r2); al[2] = tf32_bits(r2 - __uint_as_float(ah[2]));
                ah[3] = tf32_bits(r3); al[3] = tf32_bits(r3 - __uint_as_float(ah[3]));
                #pragma unroll
                for (int nb = 0; nb < 4; nb++) {
                    mma8(acc[mb][nb], ah, bh[nb][0], bh[nb][1]);
                    mma8(acc[mb][nb], ah, bl[nb][0], bl[nb][1]);
                    mma8(acc[mb][nb], al, bh[nb][0], bh[nb][1]);
                }
            }
        }
        __syncthreads();
    }

    // ---- epilogue (R11-validated mapping) ----
    int m_base = m0 + mwarp;
    int n_base = n0 + (wid >> 1) * 32;
    #pragma unroll
    for (int mb = 0; mb < 4; mb++) {
        int row = m_base + mb * 16 + g;
        #pragma unroll
        for (int nb = 0; nb < 4; nb++) {
            int col = n_base + nb * 8 + 2 * t;
            float v0 = acc[mb][nb][0], v1 = acc[mb][nb][1];
            float v2 = acc[mb][nb][2], v3 = acc[mb][nb][3];
            if (EPI & 1) {
                float2 bb = *(const float2*)&bias[col];
                v0 += bb.x; v1 += bb.y; v2 += bb.x; v3 += bb.y;
            }
            if (EPI & 2) {
                v0 = gelu_f(v0); v1 = gelu_f(v1); v2 = gelu_f(v2); v3 = gelu_f(v3);
            }
            if (EPI & 4) {
                float2 r0 = *(const float2*)&R[(size_t)row * 256 + col];
                float2 r1 = *(const float2*)&R[(size_t)(row + 8) * 256 + col];
                v0 += r0.x; v1 += r0.y; v2 += r1.x; v3 += r1.y;
            }
            *(float2*)&C[(size_t)row * 256 + col]       = make_float2(v0, v1);
            *(float2*)&C[(size_t)(row + 8) * 256 + col] = make_float2(v2, v3);
        }
    }
}

// ---- final projection + diffusion update ----
__global__ void final_update_kernel(const float* __restrict__ fw, const float* __restrict__ fb,
                                    int step, float c1, float sqrt_a, float sqrt_b,
                                    int add_noise, float* out)
{
    __shared__ float sfw[HDIM * 4];
    int tid = threadIdx.x;
    #pragma unroll
    for (int l = 0; l < 4; l++) sfw[tid + l * 256] = fw[tid + l * 256];
    __syncthreads();
    int m = blockIdx.x * 64 + (tid >> 2), a = tid & 3;
    const float4* h4 = (const float4*)&g_h[(size_t)m * HDIM];
    float acc = 0.0f;
    #pragma unroll 8
    for (int k4 = 0; k4 < HDIM / 4; k4++) {
        float4 hv = h4[k4];
        acc = fmaf(hv.x, sfw[(k4*4+0)*4+a], acc);
        acc = fmaf(hv.y, sfw[(k4*4+1)*4+a], acc);
        acc = fmaf(hv.z, sfw[(k4*4+2)*4+a], acc);
        acc = fmaf(hv.w, sfw[(k4*4+3)*4+a], acc);
    }
    float pred = acc + fb[a];
    float x = g_x[m*4+a];
    x = (x - c1 * pred) / sqrt_a;
    if (add_noise) x += sqrt_b * g_noise[((size_t)step * BSZ + m) * 4 + a];
    g_x[m*4+a] = x;
    if (out) out[m*4+a] = fminf(1.0f, fmaxf(-1.0f, x));
}

// ---- launch ----
extern "C" void kernel_launch(void* const* d_in, const int* in_sizes, int n_in,
                              void* d_out, int out_size)
{
    (void)n_in; (void)out_size;
    const float *features, *cond_w, *cond_b, *time_w, *time_b;
    const float *blk0_w1, *blk0_b1, *blk0_w2, *blk0_b2, *blk0_skip_w, *blk0_skip_b;
    const float *blks_w1, *blks_b1, *blks_w2, *blks_b2, *final_w, *final_b;

    if (in_sizes[0] == BSZ * HDIM) {
        features    = (const float*)d_in[0];  cond_w      = (const float*)d_in[1];
        cond_b      = (const float*)d_in[2];  time_w      = (const float*)d_in[3];
        time_b      = (const float*)d_in[4];  blk0_w1     = (const float*)d_in[5];
        blk0_b1     = (const float*)d_in[6];  blk0_w2     = (const float*)d_in[7];
        blk0_b2     = (const float*)d_in[8];  blk0_skip_w = (const float*)d_in[9];
        blk0_skip_b = (const float*)d_in[10]; blks_w1     = (const float*)d_in[11];
        blks_b1     = (const float*)d_in[12]; blks_w2     = (const float*)d_in[13];
        blks_b2     = (const float*)d_in[14]; final_w     = (const float*)d_in[15];
        final_b     = (const float*)d_in[16];
    } else {
        blk0_b1     = (const float*)d_in[0];  blk0_b2     = (const float*)d_in[1];
        blk0_skip_b = (const float*)d_in[2];  blk0_skip_w = (const float*)d_in[3];
        blk0_w1     = (const float*)d_in[4];  blk0_w2     = (const float*)d_in[5];
        blks_b1     = (const float*)d_in[6];  blks_b2     = (const float*)d_in[7];
        blks_w1     = (const float*)d_in[8];  blks_w2     = (const float*)d_in[9];
        cond_b      = (const float*)d_in[10]; cond_w      = (const float*)d_in[11];
        features    = (const float*)d_in[12]; final_b     = (const float*)d_in[13];
        final_w     = (const float*)d_in[14]; time_b      = (const float*)d_in[15];
        time_w      = (const float*)d_in[16];
    }

    float *p_cond1, *p_cskip, *p_h, *p_t, *p_skip, *p_x, *p_noise, *p_wfh, *p_wfl;
    cudaGetSymbolAddress((void**)&p_cond1, g_cond1);
    cudaGetSymbolAddress((void**)&p_cskip, g_cskip);
    cudaGetSymbolAddress((void**)&p_h,     g_h);
    cudaGetSymbolAddress((void**)&p_t,     g_t);
    cudaGetSymbolAddress((void**)&p_skip,  g_skip);
    cudaGetSymbolAddress((void**)&p_x,     g_x);
    cudaGetSymbolAddress((void**)&p_noise, g_noise);
    cudaGetSymbolAddress((void**)&p_wfh,   g_wfh);
    cudaGetSymbolAddress((void**)&p_wfl,   g_wfl);

    float betas[100], acps[100], cp = 1.0f;
    for (int i = 0; i < 100; i++) {
        betas[i] = (float)(1e-4 + (0.02 - 1e-4) * ((double)i / 99.0));
        cp *= (1.0f - betas[i]);
        acps[i] = cp;
    }
    unsigned kx0, kx1, kn0, kn1;
    threefry2x32(0u, 42u, 0u, 999u, kx0, kx1);
    threefry2x32(0u, 42u, 0u, 7u,   kn0, kn1);

    rng_normal_kernel<<<512, 256>>>(p_x, BSZ * 4, kx0, kx1);
    rng_normal_kernel<<<5120, 256>>>(p_noise, INF_STEPS * BSZ * 4, kn0, kn1);
    temb_kernel<<<INF_STEPS, 256>>>(time_w, time_b, blk0_w1, blk0_skip_w);

    const float* srcs[10] = { cond_w, blk0_w1, blk0_skip_w, blk0_w2,
                              blks_w1, blks_w1 + 65536, blks_w1 + 131072,
                              blks_w2, blks_w2 + 65536, blks_w2 + 131072 };
    for (int i = 0; i < 10; i++)
        split_w_kernel<<<256, 256>>>(srcs[i], p_wfh + i * 65536, p_wfl + i * 65536);

    dim3 gg(2, BSZ / 128);
    #define WT(i) (p_wfh + (i) * 65536), (p_wfl + (i) * 65536)

    tgemm_kernel<1><<<gg, 256>>>(features, WT(0), cond_b, nullptr, p_h);
    tgemm_kernel<1><<<gg, 256>>>(p_h, WT(1), blk0_b1, nullptr, p_cond1);
    tgemm_kernel<1><<<gg, 256>>>(p_h, WT(2), blk0_skip_b, nullptr, p_cskip);

    for (int s = 0; s < INF_STEPS; s++) {
        int t = 90 - 10 * s;
        float b = betas[t], a = 1.0f - b, acp = acps[t];
        float c1 = b / sqrtf(1.0f - acp), sa = sqrtf(a), sb = sqrtf(b);

        build_kernel<<<BSZ, 256>>>(blk0_w1, blk0_skip_w, s);
        tgemm_kernel<7><<<gg, 256>>>(p_t, WT(3), blk0_b2, p_skip, p_h);
        for (int i = 0; i < 3; i++) {
            tgemm_kernel<3><<<gg, 256>>>(p_h, WT(4 + i), blks_b1 + i * 256, nullptr, p_t);
            tgemm_kernel<7><<<gg, 256>>>(p_t, WT(7 + i), blks_b2 + i * 256, p_h, p_h);
        }
        final_update_kernel<<<BSZ / 64, 256>>>(final_w, final_b, s, c1, sa, sb,
                                               (t > 0) ? 1 : 0,
                                               (s == INF_STEPS - 1) ? (float*)d_out : nullptr);
    }
    #undef WT
}